// round 1
// baseline (speedup 1.0000x reference)
#include <cuda_runtime.h>
#include <math.h>

// Problem dims (fixed)
#define B_ 1024
#define T_ 128
#define F_ 32
#define E_ 16
#define H_ 20
#define G_ 80      // 4*H
#define D_ 4096    // T*F

// Scratch (no allocations allowed -> __device__ globals)
__device__ float g_fc1[B_ * D_];   // relu(flat @ fc1_w + b)   (16.7 MB)
__device__ float g_w[B_ * E_];     // softmax gate weights
__device__ float g_eo[E_ * B_];    // per-expert outputs

__device__ __forceinline__ float sigmoidf_(float x) {
    return 1.0f / (1.0f + __expf(-x));
}

// ---------------------------------------------------------------------------
// fc1: g_fc1 = relu(x_flat[1024,4096] @ W[4096,4096] + bias)
// tile 64(M) x 128(N) x 16(K), 256 threads, 4x8 microtile -> 512 blocks
// ---------------------------------------------------------------------------
#define FBM 64
#define FBN 128
#define FBK 16
#define FTM 4
#define FTN 8

__global__ void __launch_bounds__(256) fc1_kernel(
    const float* __restrict__ A, const float* __restrict__ W,
    const float* __restrict__ bias)
{
    __shared__ __align__(16) float As[FBK][FBM + 4];  // padded, stored transposed
    __shared__ __align__(16) float Ws[FBK][FBN];

    const int bx = blockIdx.x;          // N tile 0..31
    const int by = blockIdx.y;          // M tile 0..15
    const int tid = threadIdx.x;
    const int tx = tid & 15;            // N dir (16 * 8 = 128)
    const int ty = tid >> 4;            // M dir (16 * 4 = 64)

    const int a_row = tid >> 2;         // 0..63
    const int a_col = (tid & 3) << 2;   // 0,4,8,12
    const int w_row = tid >> 5;         // 0..7 (+8 for second load)
    const int w_col = (tid & 31) << 2;

    const float* Ap = A + (size_t)(by * FBM + a_row) * D_ + a_col;
    const float* Wp = W + (size_t)w_row * D_ + bx * FBN + w_col;

    float acc[FTM][FTN];
    #pragma unroll
    for (int i = 0; i < FTM; i++)
        #pragma unroll
        for (int j = 0; j < FTN; j++) acc[i][j] = 0.f;

    for (int k0 = 0; k0 < D_; k0 += FBK) {
        float4 av = *(const float4*)(Ap + k0);
        As[a_col + 0][a_row] = av.x;
        As[a_col + 1][a_row] = av.y;
        As[a_col + 2][a_row] = av.z;
        As[a_col + 3][a_row] = av.w;
        float4 wv0 = *(const float4*)(Wp + (size_t)k0 * D_);
        float4 wv1 = *(const float4*)(Wp + (size_t)(k0 + 8) * D_);
        *(float4*)&Ws[w_row][w_col] = wv0;
        *(float4*)&Ws[w_row + 8][w_col] = wv1;
        __syncthreads();
        #pragma unroll
        for (int k = 0; k < FBK; k++) {
            float4 a4 = *(const float4*)&As[k][ty * FTM];
            float4 w0 = *(const float4*)&Ws[k][tx * FTN];
            float4 w1 = *(const float4*)&Ws[k][tx * FTN + 4];
            float af[4] = {a4.x, a4.y, a4.z, a4.w};
            float wf[8] = {w0.x, w0.y, w0.z, w0.w, w1.x, w1.y, w1.z, w1.w};
            #pragma unroll
            for (int i = 0; i < FTM; i++)
                #pragma unroll
                for (int j = 0; j < FTN; j++)
                    acc[i][j] += af[i] * wf[j];
        }
        __syncthreads();
    }

    const int crow = by * FBM + ty * FTM;
    const int ccol = bx * FBN + tx * FTN;
    float bw[FTN];
    #pragma unroll
    for (int j = 0; j < FTN; j++) bw[j] = bias[ccol + j];
    #pragma unroll
    for (int i = 0; i < FTM; i++) {
        float4 o0, o1;
        o0.x = fmaxf(acc[i][0] + bw[0], 0.f);
        o0.y = fmaxf(acc[i][1] + bw[1], 0.f);
        o0.z = fmaxf(acc[i][2] + bw[2], 0.f);
        o0.w = fmaxf(acc[i][3] + bw[3], 0.f);
        o1.x = fmaxf(acc[i][4] + bw[4], 0.f);
        o1.y = fmaxf(acc[i][5] + bw[5], 0.f);
        o1.z = fmaxf(acc[i][6] + bw[6], 0.f);
        o1.w = fmaxf(acc[i][7] + bw[7], 0.f);
        *(float4*)&g_fc1[(size_t)(crow + i) * D_ + ccol] = o0;
        *(float4*)&g_fc1[(size_t)(crow + i) * D_ + ccol + 4] = o1;
    }
}

// ---------------------------------------------------------------------------
// gate: logits = g_fc1[b,:] @ gate_w[4096,16] + gate_b ; g_w[b,:] = softmax
// one block per batch row, 256 threads
// ---------------------------------------------------------------------------
__global__ void __launch_bounds__(256) gate_kernel(
    const float* __restrict__ GW, const float* __restrict__ GB)
{
    const int b = blockIdx.x;
    const int tid = threadIdx.x;
    float acc[E_];
    #pragma unroll
    for (int e = 0; e < E_; e++) acc[e] = 0.f;

    const float* grow = g_fc1 + (size_t)b * D_;
    for (int k = tid; k < D_; k += 256) {
        float gv = grow[k];
        const float4* wp = (const float4*)(GW + (size_t)k * E_);
        float4 w0 = wp[0], w1 = wp[1], w2 = wp[2], w3 = wp[3];
        acc[0]  += gv * w0.x;  acc[1]  += gv * w0.y;
        acc[2]  += gv * w0.z;  acc[3]  += gv * w0.w;
        acc[4]  += gv * w1.x;  acc[5]  += gv * w1.y;
        acc[6]  += gv * w1.z;  acc[7]  += gv * w1.w;
        acc[8]  += gv * w2.x;  acc[9]  += gv * w2.y;
        acc[10] += gv * w2.z;  acc[11] += gv * w2.w;
        acc[12] += gv * w3.x;  acc[13] += gv * w3.y;
        acc[14] += gv * w3.z;  acc[15] += gv * w3.w;
    }

    // warp reduce each of the 16 partials
    #pragma unroll
    for (int e = 0; e < E_; e++) {
        #pragma unroll
        for (int off = 16; off > 0; off >>= 1)
            acc[e] += __shfl_down_sync(0xffffffffu, acc[e], off);
    }
    __shared__ float red[8][E_];
    const int warp = tid >> 5, lane = tid & 31;
    if (lane == 0) {
        #pragma unroll
        for (int e = 0; e < E_; e++) red[warp][e] = acc[e];
    }
    __syncthreads();

    __shared__ float sv[E_];
    if (tid < E_) {
        float s = GB[tid];
        #pragma unroll
        for (int w = 0; w < 8; w++) s += red[w][tid];
        sv[tid] = s;
    }
    __syncthreads();
    __shared__ float ev[E_];
    if (tid < E_) {
        float m = sv[0];
        #pragma unroll
        for (int e = 1; e < E_; e++) m = fmaxf(m, sv[e]);
        ev[tid] = expf(sv[tid] - m);
    }
    __syncthreads();
    if (tid < E_) {
        float s = 0.f;
        #pragma unroll
        for (int e = 0; e < E_; e++) s += ev[e];
        g_w[b * E_ + tid] = ev[tid] / s;
    }
}

// ---------------------------------------------------------------------------
// lstm: per (expert, 4 batch rows) block. 320 threads = 4 rows x 80 gates.
// Weights live in registers (column g of each matrix). Both LSTM layers fused
// in one time loop; BatchNorm fused into the x_t load. Dense head at the end.
// ---------------------------------------------------------------------------
#define LROWS 4
#define LTHREADS (LROWS * G_)   // 320

__global__ void __launch_bounds__(LTHREADS, 1) lstm_kernel(
    const float* __restrict__ x,
    const float* __restrict__ bn_gamma, const float* __restrict__ bn_beta,
    const float* __restrict__ bn_mean,  const float* __restrict__ bn_var,
    const float* __restrict__ k1, const float* __restrict__ r1, const float* __restrict__ b1,
    const float* __restrict__ k2, const float* __restrict__ r2, const float* __restrict__ b2,
    const float* __restrict__ dw, const float* __restrict__ db)
{
    const int e = blockIdx.y;
    const int row0 = blockIdx.x * LROWS;
    const int tid = threadIdx.x;
    const int r = tid / G_;        // 0..3
    const int g = tid - r * G_;    // 0..79

    __shared__ float bn_scale[F_], bn_shift[F_];
    __shared__ __align__(16) float xt_s[LROWS][F_];
    __shared__ __align__(16) float h1_s[LROWS][H_];
    __shared__ __align__(16) float h2_s[LROWS][H_];
    __shared__ float z1_s[LROWS][G_];
    __shared__ float z2_s[LROWS][G_];

    if (tid < F_) {
        float sc = bn_gamma[tid] * rsqrtf(bn_var[tid] + 1e-3f);
        bn_scale[tid] = sc;
        bn_shift[tid] = bn_beta[tid] - bn_mean[tid] * sc;
    }
    if (tid < LROWS * H_) {
        ((float*)h1_s)[tid] = 0.f;
        ((float*)h2_s)[tid] = 0.f;
    }

    // register-resident weight columns (94 values / thread)
    float wk1[F_], wr1[H_], wk2[H_], wr2[H_];
    #pragma unroll
    for (int k = 0; k < F_; k++) wk1[k] = k1[(e * F_ + k) * G_ + g];
    #pragma unroll
    for (int j = 0; j < H_; j++) wr1[j] = r1[(e * H_ + j) * G_ + g];
    #pragma unroll
    for (int j = 0; j < H_; j++) wk2[j] = k2[(e * H_ + j) * G_ + g];
    #pragma unroll
    for (int j = 0; j < H_; j++) wr2[j] = r2[(e * H_ + j) * G_ + g];
    const float bias1 = b1[e * G_ + g];
    const float bias2 = b2[e * G_ + g];

    float c1 = 0.f, c2 = 0.f;   // used by cell threads (g < H_)

    __syncthreads();

    for (int t = 0; t < T_; t++) {
        // S1: stage x_t (BatchNorm fused)
        if (tid < LROWS * F_) {
            int rr = tid >> 5;
            int f  = tid & 31;
            float xv = x[(size_t)(row0 + rr) * (T_ * F_) + t * F_ + f];
            xt_s[rr][f] = xv * bn_scale[f] + bn_shift[f];
        }
        __syncthreads();  // B1: xt ready; prev h2/z2 hazards cleared

        // S2: z1 = b1 + x_t @ Wk1 + h1 @ Wr1   (52 FMA, 4 accumulators)
        float za = bias1, zb = 0.f, zc = 0.f, zd = 0.f;
        const float4* xr = (const float4*)xt_s[r];
        #pragma unroll
        for (int k = 0; k < 8; k++) {
            float4 v = xr[k];
            za += v.x * wk1[4*k+0];
            zb += v.y * wk1[4*k+1];
            zc += v.z * wk1[4*k+2];
            zd += v.w * wk1[4*k+3];
        }
        const float4* h1r = (const float4*)h1_s[r];
        #pragma unroll
        for (int j = 0; j < 5; j++) {
            float4 v = h1r[j];
            za += v.x * wr1[4*j+0];
            zb += v.y * wr1[4*j+1];
            zc += v.z * wr1[4*j+2];
            zd += v.w * wr1[4*j+3];
        }
        z1_s[r][g] = (za + zb) + (zc + zd);

        // overlap: LSTM2 recurrent partial against previous-step h2
        float ya = bias2, yb = 0.f, yc = 0.f, yd = 0.f;
        const float4* h2r = (const float4*)h2_s[r];
        #pragma unroll
        for (int j = 0; j < 5; j++) {
            float4 v = h2r[j];
            ya += v.x * wr2[4*j+0];
            yb += v.y * wr2[4*j+1];
            yc += v.z * wr2[4*j+2];
            yd += v.w * wr2[4*j+3];
        }
        __syncthreads();  // B2: z1_s ready

        // S3: LSTM1 cell update (gate order i,f,g,o; g-act = relu, h = o*relu(c))
        if (g < H_) {
            float iv = sigmoidf_(z1_s[r][g]);
            float fv = sigmoidf_(z1_s[r][H_ + g]);
            float gv = fmaxf(z1_s[r][2*H_ + g], 0.f);
            float ov = sigmoidf_(z1_s[r][3*H_ + g]);
            c1 = fv * c1 + iv * gv;
            h1_s[r][g] = ov * fmaxf(c1, 0.f);
        }
        __syncthreads();  // B3: h1_s ready

        // S4: z2 += h1_t @ Wk2
        const float4* h1n = (const float4*)h1_s[r];
        #pragma unroll
        for (int j = 0; j < 5; j++) {
            float4 v = h1n[j];
            ya += v.x * wk2[4*j+0];
            yb += v.y * wk2[4*j+1];
            yc += v.z * wk2[4*j+2];
            yd += v.w * wk2[4*j+3];
        }
        z2_s[r][g] = (ya + yb) + (yc + yd);
        __syncthreads();  // B4: z2_s ready

        // S5: LSTM2 cell update (next read of h2_s is after next B1)
        if (g < H_) {
            float iv = sigmoidf_(z2_s[r][g]);
            float fv = sigmoidf_(z2_s[r][H_ + g]);
            float gv = fmaxf(z2_s[r][2*H_ + g], 0.f);
            float ov = sigmoidf_(z2_s[r][3*H_ + g]);
            c2 = fv * c2 + iv * gv;
            h2_s[r][g] = ov * fmaxf(c2, 0.f);
        }
    }
    __syncthreads();  // final h2_s visible

    // dense head: eo[e,b] = h2 @ dw[e] + db[e]
    if (g == 0) {
        float acc = db[e];
        #pragma unroll
        for (int j = 0; j < H_; j++) acc += h2_s[r][j] * dw[e * H_ + j];
        g_eo[e * B_ + row0 + r] = acc;
    }
}

// ---------------------------------------------------------------------------
// combine: out[b] = sum_e eo[e,b] * w[b,e]
// ---------------------------------------------------------------------------
__global__ void combine_kernel(float* __restrict__ out)
{
    int b = blockIdx.x * blockDim.x + threadIdx.x;
    if (b < B_) {
        float s = 0.f;
        #pragma unroll
        for (int e = 0; e < E_; e++)
            s += g_eo[e * B_ + b] * g_w[b * E_ + e];
        out[b] = s;
    }
}

// ---------------------------------------------------------------------------
extern "C" void kernel_launch(void* const* d_in, const int* in_sizes, int n_in,
                              void* d_out, int out_size)
{
    const float* x        = (const float*)d_in[0];
    const float* bn_gamma = (const float*)d_in[1];
    const float* bn_beta  = (const float*)d_in[2];
    const float* bn_mean  = (const float*)d_in[3];
    const float* bn_var   = (const float*)d_in[4];
    const float* k1       = (const float*)d_in[5];
    const float* r1       = (const float*)d_in[6];
    const float* b1       = (const float*)d_in[7];
    const float* k2       = (const float*)d_in[8];
    const float* r2       = (const float*)d_in[9];
    const float* b2       = (const float*)d_in[10];
    const float* dw       = (const float*)d_in[11];
    const float* db       = (const float*)d_in[12];
    const float* fc1_w    = (const float*)d_in[13];
    const float* fc1_b    = (const float*)d_in[14];
    const float* gate_w   = (const float*)d_in[15];
    const float* gate_b   = (const float*)d_in[16];
    float* out = (float*)d_out;

    // LSTM path (independent of gating path)
    dim3 lgrid(B_ / LROWS, E_);
    lstm_kernel<<<lgrid, LTHREADS>>>(x, bn_gamma, bn_beta, bn_mean, bn_var,
                                     k1, r1, b1, k2, r2, b2, dw, db);

    // Gating path
    dim3 fgrid(D_ / FBN, B_ / FBM);   // (32, 16)
    fc1_kernel<<<fgrid, 256>>>(x, fc1_w, fc1_b);
    gate_kernel<<<B_, 256>>>(gate_w, gate_b);

    // Final mixture
    combine_kernel<<<B_ / 256, 256>>>(out);
}

// round 2
// speedup vs baseline: 1.4431x; 1.4431x over previous
#include <cuda_runtime.h>
#include <math.h>

// Problem dims (fixed)
#define B_ 1024
#define T_ 128
#define F_ 32
#define E_ 16
#define H_ 20
#define G_ 80      // 4*H
#define D_ 4096    // T*F

// Scratch (no allocations allowed -> __device__ globals)
__device__ float g_fc1[B_ * D_];            // relu(flat @ fc1_w + b)  (16.7 MB)
__device__ float g_h1[E_ * B_ * T_ * H_];   // layer-1 hidden sequences (168 MB)
__device__ float g_w[B_ * E_];              // softmax gate weights
__device__ float g_eo[E_ * B_];             // per-expert outputs

__device__ __forceinline__ float sigmoidf_(float x) {
    return 1.0f / (1.0f + __expf(-x));
}

// ---------------------------------------------------------------------------
// K1: fat kernel = fc1 GEMM (blocks [0,512)) + LSTM layer 1 (blocks [512,4608))
// 320 threads, 2 CTA/SM target.
// ---------------------------------------------------------------------------
#define FC1_BLOCKS 512
#define L_BLOCKS   4096      // 256 row-groups x 16 experts
#define LROWS 4

struct SFC {                  // fc1 tile buffers (12544 B)
    float As[16][68];         // transposed, padded
    float Ws[16][128];
};
struct SP1 {                  // lstm layer-1 buffers
    float bns[F_], bnh[F_];
    float xt[LROWS][F_];
    float h1[LROWS][24];      // row stride 24 floats (96B) for aligned float4
    float z1[LROWS][G_];
};
union U1 { SFC f; SP1 p; };

__global__ void __launch_bounds__(320, 2) k1_fc1_lstm1(
    const float* __restrict__ x, const float* __restrict__ fc1_w,
    const float* __restrict__ fc1_b,
    const float* __restrict__ bn_gamma, const float* __restrict__ bn_beta,
    const float* __restrict__ bn_mean,  const float* __restrict__ bn_var,
    const float* __restrict__ k1, const float* __restrict__ r1,
    const float* __restrict__ b1)
{
    __shared__ __align__(16) U1 u;
    const int tid = threadIdx.x;

    if (blockIdx.x < FC1_BLOCKS) {
        // ----------------- fc1: 64x128x16 tile, 256 active threads ----------
        const int bx = blockIdx.x & 31;   // N tile (32)
        const int by = blockIdx.x >> 5;   // M tile (16)
        const bool act = tid < 256;

        const int tx = tid & 15;
        const int ty = tid >> 4;
        const int a_row = tid >> 2;
        const int a_col = (tid & 3) << 2;
        const int w_row = (tid >> 5) & 7;
        const int w_col = (tid & 31) << 2;

        const float* Ap = x + (size_t)(by * 64 + a_row) * D_ + a_col;
        const float* Wp = fc1_w + (size_t)w_row * D_ + bx * 128 + w_col;

        float acc[4][8];
        #pragma unroll
        for (int i = 0; i < 4; i++)
            #pragma unroll
            for (int j = 0; j < 8; j++) acc[i][j] = 0.f;

        float4 av = make_float4(0,0,0,0), wv0 = av, wv1 = av;
        if (act) {
            av  = *(const float4*)(Ap);
            wv0 = *(const float4*)(Wp);
            wv1 = *(const float4*)(Wp + (size_t)8 * D_);
        }

        for (int k0 = 0; k0 < D_; k0 += 16) {
            if (act) {
                u.f.As[a_col + 0][a_row] = av.x;
                u.f.As[a_col + 1][a_row] = av.y;
                u.f.As[a_col + 2][a_row] = av.z;
                u.f.As[a_col + 3][a_row] = av.w;
                *(float4*)&u.f.Ws[w_row][w_col] = wv0;
                *(float4*)&u.f.Ws[w_row + 8][w_col] = wv1;
            }
            __syncthreads();
            if (act && k0 + 16 < D_) {   // prefetch next slab during compute
                av  = *(const float4*)(Ap + k0 + 16);
                wv0 = *(const float4*)(Wp + (size_t)(k0 + 16) * D_);
                wv1 = *(const float4*)(Wp + (size_t)(k0 + 24) * D_);
            }
            if (act) {
                #pragma unroll
                for (int k = 0; k < 16; k++) {
                    float4 a4 = *(const float4*)&u.f.As[k][ty * 4];
                    float4 w0 = *(const float4*)&u.f.Ws[k][tx * 8];
                    float4 w1 = *(const float4*)&u.f.Ws[k][tx * 8 + 4];
                    float af[4] = {a4.x, a4.y, a4.z, a4.w};
                    float wf[8] = {w0.x, w0.y, w0.z, w0.w, w1.x, w1.y, w1.z, w1.w};
                    #pragma unroll
                    for (int i = 0; i < 4; i++)
                        #pragma unroll
                        for (int j = 0; j < 8; j++)
                            acc[i][j] += af[i] * wf[j];
                }
            }
            __syncthreads();
        }

        if (act) {
            const int crow = by * 64 + ty * 4;
            const int ccol = bx * 128 + tx * 8;
            float bw[8];
            #pragma unroll
            for (int j = 0; j < 8; j++) bw[j] = fc1_b[ccol + j];
            #pragma unroll
            for (int i = 0; i < 4; i++) {
                float4 o0, o1;
                o0.x = fmaxf(acc[i][0] + bw[0], 0.f);
                o0.y = fmaxf(acc[i][1] + bw[1], 0.f);
                o0.z = fmaxf(acc[i][2] + bw[2], 0.f);
                o0.w = fmaxf(acc[i][3] + bw[3], 0.f);
                o1.x = fmaxf(acc[i][4] + bw[4], 0.f);
                o1.y = fmaxf(acc[i][5] + bw[5], 0.f);
                o1.z = fmaxf(acc[i][6] + bw[6], 0.f);
                o1.w = fmaxf(acc[i][7] + bw[7], 0.f);
                *(float4*)&g_fc1[(size_t)(crow + i) * D_ + ccol]     = o0;
                *(float4*)&g_fc1[(size_t)(crow + i) * D_ + ccol + 4] = o1;
            }
        }
        return;
    }

    // --------------------- LSTM layer 1 ------------------------------------
    const int idx = blockIdx.x - FC1_BLOCKS;
    const int e = idx >> 8;
    const int row0 = (idx & 255) * LROWS;
    const int r = tid / G_;
    const int g = tid - r * G_;

    if (tid < F_) {
        float sc = bn_gamma[tid] * rsqrtf(bn_var[tid] + 1e-3f);
        u.p.bns[tid] = sc;
        u.p.bnh[tid] = bn_beta[tid] - bn_mean[tid] * sc;
    }
    if (tid < LROWS * H_) u.p.h1[tid / H_][tid % H_] = 0.f;

    // register weight column g of k1/r1
    float wk1[F_], wr1[H_];
    #pragma unroll
    for (int k = 0; k < F_; k++) wk1[k] = k1[(e * F_ + k) * G_ + g];
    #pragma unroll
    for (int j = 0; j < H_; j++) wr1[j] = r1[(e * H_ + j) * G_ + g];
    const float bias1 = b1[e * G_ + g];

    const bool sx = tid < LROWS * F_;        // x staging threads
    const int rr = tid >> 5, f = tid & 31;
    const float* px = x + (size_t)(row0 + rr) * (T_ * F_) + f;
    float c1 = 0.f, xv = 0.f, sc = 0.f, sh = 0.f;

    __syncthreads();                          // bn tables ready
    if (sx) {
        sc = u.p.bns[f]; sh = u.p.bnh[f];
        u.p.xt[rr][f] = px[0] * sc + sh;      // stage x(0)
        xv = px[F_];                          // prefetch x(1)
    }
    __syncthreads();

    float* hrow = g_h1 + ((size_t)(e * B_ + row0 + r) * T_) * H_ + g;

    for (int t = 0; t < T_; t++) {
        // z1 = b1 + x_t @ Wk1 + h1 @ Wr1
        float za = bias1, zb = 0.f, zc = 0.f, zd = 0.f;
        const float4* xr = (const float4*)u.p.xt[r];
        #pragma unroll
        for (int k = 0; k < 8; k++) {
            float4 v = xr[k];
            za += v.x * wk1[4*k+0];
            zb += v.y * wk1[4*k+1];
            zc += v.z * wk1[4*k+2];
            zd += v.w * wk1[4*k+3];
        }
        const float4* h1r = (const float4*)u.p.h1[r];
        #pragma unroll
        for (int j = 0; j < 5; j++) {
            float4 v = h1r[j];
            za += v.x * wr1[4*j+0];
            zb += v.y * wr1[4*j+1];
            zc += v.z * wr1[4*j+2];
            zd += v.w * wr1[4*j+3];
        }
        u.p.z1[r][g] = (za + zb) + (zc + zd);
        __syncthreads();                      // z1 ready; xt/h1 free

        if (g < H_) {
            float iv = sigmoidf_(u.p.z1[r][g]);
            float fv = sigmoidf_(u.p.z1[r][H_ + g]);
            float gv = fmaxf(u.p.z1[r][2*H_ + g], 0.f);
            float ov = sigmoidf_(u.p.z1[r][3*H_ + g]);
            c1 = fv * c1 + iv * gv;
            float h = ov * fmaxf(c1, 0.f);
            u.p.h1[r][g] = h;
            hrow[t * H_] = h;                 // stream to g_h1
        }
        if (sx) {
            u.p.xt[rr][f] = xv * sc + sh;     // stage x(t+1)
            int tn = (t + 2 < T_) ? t + 2 : T_ - 1;
            xv = px[tn * F_];                 // prefetch
        }
        __syncthreads();                      // h1(t), xt(t+1) ready
    }
}

// ---------------------------------------------------------------------------
// K2: fat kernel = gate (blocks [0,1024)) + LSTM layer 2 (blocks [1024,5120))
// ---------------------------------------------------------------------------
struct SG {
    float red[10][E_];
    float sv[E_];
    float ev[E_];
};
struct SP2 {
    float h1t[LROWS][24];
    float h2[LROWS][24];
    float z2[LROWS][G_];
};
union U2 { SG g; SP2 p; };

__global__ void __launch_bounds__(320, 2) k2_gate_lstm2(
    const float* __restrict__ GW, const float* __restrict__ GB,
    const float* __restrict__ k2, const float* __restrict__ r2,
    const float* __restrict__ b2,
    const float* __restrict__ dw, const float* __restrict__ db)
{
    __shared__ __align__(16) U2 u;
    const int tid = threadIdx.x;

    if (blockIdx.x < B_) {
        // ----------------- gate: logits + softmax --------------------------
        const int b = blockIdx.x;
        float acc[E_];
        #pragma unroll
        for (int e = 0; e < E_; e++) acc[e] = 0.f;

        const float* grow = g_fc1 + (size_t)b * D_;
        for (int k = tid; k < D_; k += 320) {
            float gv = grow[k];
            const float4* wp = (const float4*)(GW + (size_t)k * E_);
            float4 w0 = wp[0], w1 = wp[1], w2 = wp[2], w3 = wp[3];
            acc[0]  += gv * w0.x;  acc[1]  += gv * w0.y;
            acc[2]  += gv * w0.z;  acc[3]  += gv * w0.w;
            acc[4]  += gv * w1.x;  acc[5]  += gv * w1.y;
            acc[6]  += gv * w1.z;  acc[7]  += gv * w1.w;
            acc[8]  += gv * w2.x;  acc[9]  += gv * w2.y;
            acc[10] += gv * w2.z;  acc[11] += gv * w2.w;
            acc[12] += gv * w3.x;  acc[13] += gv * w3.y;
            acc[14] += gv * w3.z;  acc[15] += gv * w3.w;
        }
        #pragma unroll
        for (int e = 0; e < E_; e++) {
            #pragma unroll
            for (int off = 16; off > 0; off >>= 1)
                acc[e] += __shfl_down_sync(0xffffffffu, acc[e], off);
        }
        const int warp = tid >> 5, lane = tid & 31;
        if (lane == 0) {
            #pragma unroll
            for (int e = 0; e < E_; e++) u.g.red[warp][e] = acc[e];
        }
        __syncthreads();
        if (tid < E_) {
            float s = GB[tid];
            #pragma unroll
            for (int w = 0; w < 10; w++) s += u.g.red[w][tid];
            u.g.sv[tid] = s;
        }
        __syncthreads();
        if (tid < E_) {
            float m = u.g.sv[0];
            #pragma unroll
            for (int e = 1; e < E_; e++) m = fmaxf(m, u.g.sv[e]);
            u.g.ev[tid] = expf(u.g.sv[tid] - m);
        }
        __syncthreads();
        if (tid < E_) {
            float s = 0.f;
            #pragma unroll
            for (int e = 0; e < E_; e++) s += u.g.ev[e];
            g_w[b * E_ + tid] = u.g.ev[tid] / s;
        }
        return;
    }

    // --------------------- LSTM layer 2 ------------------------------------
    const int idx = blockIdx.x - B_;
    const int e = idx >> 8;
    const int row0 = (idx & 255) * LROWS;
    const int r = tid / G_;
    const int g = tid - r * G_;

    if (tid < LROWS * H_) u.p.h2[tid / H_][tid % H_] = 0.f;

    float wk2[H_], wr2[H_];
    #pragma unroll
    for (int j = 0; j < H_; j++) wk2[j] = k2[(e * H_ + j) * G_ + g];
    #pragma unroll
    for (int j = 0; j < H_; j++) wr2[j] = r2[(e * H_ + j) * G_ + g];
    const float bias2 = b2[e * G_ + g];

    const bool sh1 = tid < LROWS * H_;        // h1 staging threads
    const int rr = tid / H_, hh = tid - rr * H_;
    const float* ph = g_h1 + ((size_t)(e * B_ + row0 + rr) * T_) * H_ + hh;
    float c2 = 0.f, hv = 0.f;

    if (sh1) {
        u.p.h1t[rr][hh] = ph[0];              // stage h1(0)
        hv = ph[H_];                          // prefetch h1(1)
    }
    __syncthreads();

    for (int t = 0; t < T_; t++) {
        float ya = bias2, yb = 0.f, yc = 0.f, yd = 0.f;
        const float4* h1r = (const float4*)u.p.h1t[r];
        const float4* h2r = (const float4*)u.p.h2[r];
        #pragma unroll
        for (int j = 0; j < 5; j++) {
            float4 v = h1r[j];
            ya += v.x * wk2[4*j+0];
            yb += v.y * wk2[4*j+1];
            yc += v.z * wk2[4*j+2];
            yd += v.w * wk2[4*j+3];
        }
        #pragma unroll
        for (int j = 0; j < 5; j++) {
            float4 v = h2r[j];
            ya += v.x * wr2[4*j+0];
            yb += v.y * wr2[4*j+1];
            yc += v.z * wr2[4*j+2];
            yd += v.w * wr2[4*j+3];
        }
        u.p.z2[r][g] = (ya + yb) + (yc + yd);
        __syncthreads();                      // z2 ready; h1t/h2 free

        if (g < H_) {
            float iv = sigmoidf_(u.p.z2[r][g]);
            float fv = sigmoidf_(u.p.z2[r][H_ + g]);
            float gv = fmaxf(u.p.z2[r][2*H_ + g], 0.f);
            float ov = sigmoidf_(u.p.z2[r][3*H_ + g]);
            c2 = fv * c2 + iv * gv;
            u.p.h2[r][g] = ov * fmaxf(c2, 0.f);
        }
        if (sh1) {
            u.p.h1t[rr][hh] = hv;             // stage h1(t+1)
            int tn = (t + 2 < T_) ? t + 2 : T_ - 1;
            hv = ph[tn * H_];
        }
        __syncthreads();
    }

    // dense head: eo[e,b] = h2 @ dw[e] + db[e]
    if (g == 0) {
        float acc = db[e];
        #pragma unroll
        for (int j = 0; j < H_; j++) acc += u.p.h2[r][j] * dw[e * H_ + j];
        g_eo[e * B_ + row0 + r] = acc;
    }
}

// ---------------------------------------------------------------------------
// K3: combine
// ---------------------------------------------------------------------------
__global__ void combine_kernel(float* __restrict__ out)
{
    int b = blockIdx.x * blockDim.x + threadIdx.x;
    if (b < B_) {
        float s = 0.f;
        #pragma unroll
        for (int e = 0; e < E_; e++)
            s += g_eo[e * B_ + b] * g_w[b * E_ + e];
        out[b] = s;
    }
}

// ---------------------------------------------------------------------------
extern "C" void kernel_launch(void* const* d_in, const int* in_sizes, int n_in,
                              void* d_out, int out_size)
{
    const float* x        = (const float*)d_in[0];
    const float* bn_gamma = (const float*)d_in[1];
    const float* bn_beta  = (const float*)d_in[2];
    const float* bn_mean  = (const float*)d_in[3];
    const float* bn_var   = (const float*)d_in[4];
    const float* k1       = (const float*)d_in[5];
    const float* r1       = (const float*)d_in[6];
    const float* b1       = (const float*)d_in[7];
    const float* k2       = (const float*)d_in[8];
    const float* r2       = (const float*)d_in[9];
    const float* b2       = (const float*)d_in[10];
    const float* dw       = (const float*)d_in[11];
    const float* db       = (const float*)d_in[12];
    const float* fc1_w    = (const float*)d_in[13];
    const float* fc1_b    = (const float*)d_in[14];
    const float* gate_w   = (const float*)d_in[15];
    const float* gate_b   = (const float*)d_in[16];
    float* out = (float*)d_out;

    k1_fc1_lstm1<<<FC1_BLOCKS + L_BLOCKS, 320>>>(
        x, fc1_w, fc1_b, bn_gamma, bn_beta, bn_mean, bn_var, k1, r1, b1);

    k2_gate_lstm2<<<B_ + L_BLOCKS, 320>>>(
        gate_w, gate_b, k2, r2, b2, dw, db);

    combine_kernel<<<B_ / 256, 256>>>(out);
}

// round 3
// speedup vs baseline: 1.5754x; 1.0917x over previous
#include <cuda_runtime.h>
#include <math.h>
#include <stdint.h>

#define B_ 1024
#define T_ 128
#define F_ 32
#define E_ 16
#define H_ 20
#define G_ 80      // 4*H
#define D_ 4096    // T*F

typedef unsigned long long ull;

// scratch (__device__ globals; no allocations allowed)
__device__ float g_fc1[B_ * D_];   // relu(x_flat @ fc1_w + b)
__device__ float g_eo[E_ * B_];    // per-expert outputs

// ---------------- helpers -------------------------------------------------
__device__ __forceinline__ ull pack2(float lo, float hi) {
    ull r; asm("mov.b64 %0,{%1,%2};" : "=l"(r) : "f"(lo), "f"(hi)); return r;
}
__device__ __forceinline__ float2 unpack2(ull p) {
    float2 v; asm("mov.b64 {%0,%1},%2;" : "=f"(v.x), "=f"(v.y) : "l"(p)); return v;
}
// packed dual-FMA: d.lo += a.lo*b.lo ; d.hi += a.hi*b.hi   (sm_100+)
__device__ __forceinline__ void ffma2(ull& d, ull a, ull b) {
    asm("fma.rn.f32x2 %0,%1,%2,%0;" : "+l"(d) : "l"(a), "l"(b));
}
__device__ __forceinline__ float sigmoidf_(float x) {
    return 1.0f / (1.0f + __expf(-x));
}
__device__ __forceinline__ uint32_t s2u(const void* p) {
    uint32_t a;
    asm("{ .reg .u64 t; cvta.to.shared.u64 t, %1; cvt.u32.u64 %0, t; }"
        : "=r"(a) : "l"(p));
    return a;
}
__device__ __forceinline__ void cpa16(uint32_t dst, const void* src) {
    asm volatile("cp.async.cg.shared.global [%0],[%1],16;" :: "r"(dst), "l"(src));
}
#define CP_COMMIT() asm volatile("cp.async.commit_group;")
#define CP_WAIT(n)  asm volatile("cp.async.wait_group %0;" :: "n"(n))

// ---------------- K1: fc1 GEMM + fused 2-layer LSTM ------------------------
#define FC1_BLOCKS 256        // 8 M-tiles x 32 N-tiles (128x128x8)
#define LROWS 2

struct SFC {                        // fc1 tile buffers (24.8 KB)
    float As[2][8][260];            // A duplicated: As[k][2m]=As[k][2m+1]=A[m][k]
    float Ws[2][8][128];
};
struct SPL {                        // fused-lstm buffers (2.2 KB)
    float bns[F_], bnh[F_];
    float xt[LROWS][F_];
    float h1[LROWS][24];            // 24-float stride (alignment); [0..19] live
    float h2[LROWS][24];
    float z1[LROWS][G_];
    float z2[LROWS][G_];
};
union __align__(16) USH { SFC f; SPL p; };

__global__ void __launch_bounds__(320, 2) k1_fc1_lstm(
    const float* __restrict__ x, const float* __restrict__ fc1_w,
    const float* __restrict__ fc1_b,
    const float* __restrict__ bn_gamma, const float* __restrict__ bn_beta,
    const float* __restrict__ bn_mean,  const float* __restrict__ bn_var,
    const float* __restrict__ k1, const float* __restrict__ r1,
    const float* __restrict__ b1,
    const float* __restrict__ k2, const float* __restrict__ r2,
    const float* __restrict__ b2,
    const float* __restrict__ dw, const float* __restrict__ db)
{
    __shared__ USH u;
    const int tid = threadIdx.x;

    if (blockIdx.x < FC1_BLOCKS) {
        // ============== fc1: 128x128x8, FFMA2, cp.async double-buffer ======
        const int m0 = (blockIdx.x >> 5) * 128;
        const int n0 = (blockIdx.x & 31) * 128;
        const bool act = tid < 256;

        const int tx = tid & 15;           // N micro (8 cols)
        const int ty = (tid >> 4) & 15;    // M micro (8 rows)
        const int a_row = tid >> 1;        // 0..127
        const int a_kc  = (tid & 1) * 4;   // 0 or 4
        const int w_row = (tid >> 5) & 7;  // 0..7
        const int w_col = (tid & 31) * 4;  // 0..124

        uint32_t ws0 = s2u(&u.f.Ws[0][w_row][w_col]);
        uint32_t ws1 = s2u(&u.f.Ws[1][w_row][w_col]);
        const float* Asrc = x + (size_t)(m0 + a_row) * D_ + a_kc;
        const float* Wsrc = fc1_w + (size_t)w_row * D_ + n0 + w_col;

        float4 av = make_float4(0, 0, 0, 0);
        if (act) {
            av = *(const float4*)Asrc;
            cpa16(ws0, Wsrc);
            CP_COMMIT();
        }

        ull acc[8][4];
        #pragma unroll
        for (int i = 0; i < 8; i++)
            #pragma unroll
            for (int j = 0; j < 4; j++) acc[i][j] = 0ull;

        const int NS = D_ / 8;   // 512 slabs
        for (int s = 0; s < NS; s++) {
            const int buf = s & 1;
            if (act) {
                // store duplicated/transposed A slab
                *(ull*)&u.f.As[buf][a_kc + 0][2 * a_row] = pack2(av.x, av.x);
                *(ull*)&u.f.As[buf][a_kc + 1][2 * a_row] = pack2(av.y, av.y);
                *(ull*)&u.f.As[buf][a_kc + 2][2 * a_row] = pack2(av.z, av.z);
                *(ull*)&u.f.As[buf][a_kc + 3][2 * a_row] = pack2(av.w, av.w);
                if (s + 1 < NS) {
                    av = *(const float4*)(Asrc + (size_t)(s + 1) * 8);
                    cpa16(buf ? ws0 : ws1, Wsrc + (size_t)(s + 1) * 8 * D_);
                    CP_COMMIT();
                    CP_WAIT(1);       // W(s) complete
                } else {
                    CP_WAIT(0);
                }
            }
            __syncthreads();
            if (act) {
                #pragma unroll
                for (int k = 0; k < 8; k++) {
                    const ulonglong2* ap =
                        (const ulonglong2*)&u.f.As[buf][k][2 * (ty * 8)];
                    ulonglong2 A0 = ap[0], A1 = ap[1], A2 = ap[2], A3 = ap[3];
                    const ulonglong2* wp =
                        (const ulonglong2*)&u.f.Ws[buf][k][tx * 8];
                    ulonglong2 W0 = wp[0], W1 = wp[1];
                    ull ad[8] = {A0.x, A0.y, A1.x, A1.y, A2.x, A2.y, A3.x, A3.y};
                    #pragma unroll
                    for (int i = 0; i < 8; i++) {
                        ffma2(acc[i][0], ad[i], W0.x);
                        ffma2(acc[i][1], ad[i], W0.y);
                        ffma2(acc[i][2], ad[i], W1.x);
                        ffma2(acc[i][3], ad[i], W1.y);
                    }
                }
            }
            __syncthreads();
        }

        if (act) {
            const int ccol = n0 + tx * 8;
            float bw[8];
            #pragma unroll
            for (int j = 0; j < 8; j++) bw[j] = fc1_b[ccol + j];
            #pragma unroll
            for (int i = 0; i < 8; i++) {
                const int row = m0 + ty * 8 + i;
                float2 c0 = unpack2(acc[i][0]), c1 = unpack2(acc[i][1]);
                float2 c2 = unpack2(acc[i][2]), c3 = unpack2(acc[i][3]);
                float4 o0, o1;
                o0.x = fmaxf(c0.x + bw[0], 0.f); o0.y = fmaxf(c0.y + bw[1], 0.f);
                o0.z = fmaxf(c1.x + bw[2], 0.f); o0.w = fmaxf(c1.y + bw[3], 0.f);
                o1.x = fmaxf(c2.x + bw[4], 0.f); o1.y = fmaxf(c2.y + bw[5], 0.f);
                o1.z = fmaxf(c3.x + bw[6], 0.f); o1.w = fmaxf(c3.y + bw[7], 0.f);
                *(float4*)&g_fc1[(size_t)row * D_ + ccol]     = o0;
                *(float4*)&g_fc1[(size_t)row * D_ + ccol + 4] = o1;
            }
        }
        return;
    }

    // ============== fused 2-layer LSTM (skewed pipeline) ====================
    const int lb = blockIdx.x - FC1_BLOCKS;
    const int e = lb >> 9;                 // 512 row-groups per expert
    const int row0 = (lb & 511) * LROWS;

    const bool isL1 = tid < 160;
    const int v = isL1 ? tid : tid - 160;
    const int r = (v >= 80) ? 1 : 0;
    const int g = v - r * 80;
    const bool cellth = g < H_;

    // weight columns, packed into f32x2 pairs
    ull wa[16], wb[10];
    float bias;
    if (isL1) {
        #pragma unroll
        for (int q = 0; q < 16; q++)
            wa[q] = pack2(k1[(e * F_ + 2 * q) * G_ + g],
                          k1[(e * F_ + 2 * q + 1) * G_ + g]);
        #pragma unroll
        for (int q = 0; q < 10; q++)
            wb[q] = pack2(r1[(e * H_ + 2 * q) * G_ + g],
                          r1[(e * H_ + 2 * q + 1) * G_ + g]);
        bias = b1[e * G_ + g];
    } else {
        #pragma unroll
        for (int q = 0; q < 10; q++)
            wa[q] = pack2(k2[(e * H_ + 2 * q) * G_ + g],
                          k2[(e * H_ + 2 * q + 1) * G_ + g]);
        #pragma unroll
        for (int q = 0; q < 10; q++)
            wb[q] = pack2(r2[(e * H_ + 2 * q) * G_ + g],
                          r2[(e * H_ + 2 * q + 1) * G_ + g]);
        bias = b2[e * G_ + g];
    }

    // x stagers: L2 threads with g in [32,64) -> (row r, feature g-32)
    const bool stg = (!isL1) && (g >= 32) && (g < 64);
    const int f = g - 32;
    const float* px = x + (size_t)(row0 + r) * (T_ * F_) + f;
    float sc = 0.f, sh = 0.f, xv = 0.f;

    if (tid < F_) {
        float scv = bn_gamma[tid] * rsqrtf(bn_var[tid] + 1e-3f);
        u.p.bns[tid] = scv;
        u.p.bnh[tid] = bn_beta[tid] - bn_mean[tid] * scv;
    }
    if (tid < 2 * LROWS * 24) ((float*)u.p.h1)[tid] = 0.f;   // h1 + h2
    __syncthreads();
    if (stg) {
        sc = u.p.bns[f]; sh = u.p.bnh[f];
        u.p.xt[r][f] = px[0] * sc + sh;     // x(0)
        xv = px[F_];                        // prefetch x(1)
    }
    __syncthreads();

    float c = 0.f;   // cell state (cell threads of each half)

    for (int t = 0; t <= T_; t++) {
        // ---- phase A: gate pre-activations ----
        if (isL1) {
            if (t < T_) {
                ull a0 = pack2(bias, 0.f), a1 = 0, a2 = 0, a3 = 0;
                const ulonglong2* xr = (const ulonglong2*)u.p.xt[r];
                #pragma unroll
                for (int q = 0; q < 8; q++) {
                    ulonglong2 X = xr[q];
                    if ((2 * q) & 2) { ffma2(a2, X.x, wa[2 * q]); ffma2(a3, X.y, wa[2 * q + 1]); }
                    else             { ffma2(a0, X.x, wa[2 * q]); ffma2(a1, X.y, wa[2 * q + 1]); }
                }
                const ull* hp = (const ull*)u.p.h1[r];
                #pragma unroll
                for (int q = 0; q < 10; q++) {
                    ull hv = hp[q];
                    if (q & 2) { if (q & 1) ffma2(a3, hv, wb[q]); else ffma2(a2, hv, wb[q]); }
                    else       { if (q & 1) ffma2(a1, hv, wb[q]); else ffma2(a0, hv, wb[q]); }
                }
                float2 s0 = unpack2(a0), s1 = unpack2(a1), s2 = unpack2(a2), s3 = unpack2(a3);
                u.p.z1[r][g] = ((s0.x + s0.y) + (s1.x + s1.y)) +
                               ((s2.x + s2.y) + (s3.x + s3.y));
            }
        } else {
            if (t >= 1) {
                ull a0 = pack2(bias, 0.f), a1 = 0, a2 = 0, a3 = 0;
                const ull* h1p = (const ull*)u.p.h1[r];
                const ull* h2p = (const ull*)u.p.h2[r];
                #pragma unroll
                for (int q = 0; q < 10; q++) {
                    ull hv1 = h1p[q], hv2 = h2p[q];
                    if (q & 1) { ffma2(a1, hv1, wa[q]); ffma2(a3, hv2, wb[q]); }
                    else       { ffma2(a0, hv1, wa[q]); ffma2(a2, hv2, wb[q]); }
                }
                float2 s0 = unpack2(a0), s1 = unpack2(a1), s2 = unpack2(a2), s3 = unpack2(a3);
                u.p.z2[r][g] = ((s0.x + s0.y) + (s1.x + s1.y)) +
                               ((s2.x + s2.y) + (s3.x + s3.y));
            }
        }
        __syncthreads();

        // ---- phase B: cell updates + staging ----
        if (isL1) {
            if (cellth && t < T_) {
                float zi = u.p.z1[r][g], zf = u.p.z1[r][H_ + g];
                float zg = u.p.z1[r][2 * H_ + g], zo = u.p.z1[r][3 * H_ + g];
                c = sigmoidf_(zf) * c + sigmoidf_(zi) * fmaxf(zg, 0.f);
                u.p.h1[r][g] = sigmoidf_(zo) * fmaxf(c, 0.f);
            }
        } else {
            if (cellth && t >= 1) {
                float zi = u.p.z2[r][g], zf = u.p.z2[r][H_ + g];
                float zg = u.p.z2[r][2 * H_ + g], zo = u.p.z2[r][3 * H_ + g];
                c = sigmoidf_(zf) * c + sigmoidf_(zi) * fmaxf(zg, 0.f);
                u.p.h2[r][g] = sigmoidf_(zo) * fmaxf(c, 0.f);
            }
            if (stg && t + 1 < T_) {
                u.p.xt[r][f] = xv * sc + sh;                    // x(t+1)
                int tn = (t + 2 < T_) ? t + 2 : T_ - 1;
                xv = px[(size_t)tn * F_];
            }
        }
        __syncthreads();
    }

    // dense head: eo[e,b] = h2(T-1) @ dw[e] + db[e]
    if (!isL1 && g == 0) {
        float acc = db[e];
        #pragma unroll
        for (int j = 0; j < H_; j++) acc += u.p.h2[r][j] * dw[e * H_ + j];
        g_eo[e * B_ + row0 + r] = acc;
    }
}

// ---------------- K2: gate (fc1 row @ gate_w, softmax) + combine ----------
__global__ void __launch_bounds__(320) k2_gate_combine(
    const float* __restrict__ GW, const float* __restrict__ GB,
    float* __restrict__ out)
{
    __shared__ float red[10][E_];
    __shared__ float sv[E_];
    __shared__ float ev[E_];
    __shared__ float part[E_];

    const int b = blockIdx.x;
    const int tid = threadIdx.x;
    float acc[E_];
    #pragma unroll
    for (int e = 0; e < E_; e++) acc[e] = 0.f;

    const float* grow = g_fc1 + (size_t)b * D_;
    for (int k = tid; k < D_; k += 320) {
        float gv = grow[k];
        const float4* wp = (const float4*)(GW + (size_t)k * E_);
        float4 w0 = wp[0], w1 = wp[1], w2 = wp[2], w3 = wp[3];
        acc[0]  += gv * w0.x;  acc[1]  += gv * w0.y;
        acc[2]  += gv * w0.z;  acc[3]  += gv * w0.w;
        acc[4]  += gv * w1.x;  acc[5]  += gv * w1.y;
        acc[6]  += gv * w1.z;  acc[7]  += gv * w1.w;
        acc[8]  += gv * w2.x;  acc[9]  += gv * w2.y;
        acc[10] += gv * w2.z;  acc[11] += gv * w2.w;
        acc[12] += gv * w3.x;  acc[13] += gv * w3.y;
        acc[14] += gv * w3.z;  acc[15] += gv * w3.w;
    }
    #pragma unroll
    for (int e = 0; e < E_; e++) {
        #pragma unroll
        for (int off = 16; off > 0; off >>= 1)
            acc[e] += __shfl_down_sync(0xffffffffu, acc[e], off);
    }
    const int warp = tid >> 5, lane = tid & 31;
    if (lane == 0) {
        #pragma unroll
        for (int e = 0; e < E_; e++) red[warp][e] = acc[e];
    }
    __syncthreads();
    if (tid < E_) {
        float s = GB[tid];
        #pragma unroll
        for (int w = 0; w < 10; w++) s += red[w][tid];
        sv[tid] = s;
    }
    __syncthreads();
    if (tid < E_) {
        float m = sv[0];
        #pragma unroll
        for (int e = 1; e < E_; e++) m = fmaxf(m, sv[e]);
        ev[tid] = expf(sv[tid] - m);
    }
    __syncthreads();
    if (tid < E_) {
        float s = 0.f;
        #pragma unroll
        for (int e = 0; e < E_; e++) s += ev[e];
        part[tid] = (ev[tid] / s) * g_eo[tid * B_ + b];
    }
    __syncthreads();
    if (tid == 0) {
        float s = 0.f;
        #pragma unroll
        for (int e = 0; e < E_; e++) s += part[e];
        out[b] = s;
    }
}

// ---------------------------------------------------------------------------
extern "C" void kernel_launch(void* const* d_in, const int* in_sizes, int n_in,
                              void* d_out, int out_size)
{
    const float* x        = (const float*)d_in[0];
    const float* bn_gamma = (const float*)d_in[1];
    const float* bn_beta  = (const float*)d_in[2];
    const float* bn_mean  = (const float*)d_in[3];
    const float* bn_var   = (const float*)d_in[4];
    const float* k1       = (const float*)d_in[5];
    const float* r1       = (const float*)d_in[6];
    const float* b1       = (const float*)d_in[7];
    const float* k2       = (const float*)d_in[8];
    const float* r2       = (const float*)d_in[9];
    const float* b2       = (const float*)d_in[10];
    const float* dw       = (const float*)d_in[11];
    const float* db       = (const float*)d_in[12];
    const float* fc1_w    = (const float*)d_in[13];
    const float* fc1_b    = (const float*)d_in[14];
    const float* gate_w   = (const float*)d_in[15];
    const float* gate_b   = (const float*)d_in[16];
    float* out = (float*)d_out;

    const int LSTM_BLOCKS = E_ * (B_ / LROWS);   // 8192
    k1_fc1_lstm<<<FC1_BLOCKS + LSTM_BLOCKS, 320>>>(
        x, fc1_w, fc1_b, bn_gamma, bn_beta, bn_mean, bn_var,
        k1, r1, b1, k2, r2, b2, dw, db);

    k2_gate_combine<<<B_, 320>>>(gate_w, gate_b, out);
}

// round 4
// speedup vs baseline: 1.9289x; 1.2243x over previous
#include <cuda_runtime.h>
#include <math.h>
#include <stdint.h>

#define B_ 1024
#define T_ 128
#define F_ 32
#define E_ 16
#define H_ 20
#define G_ 80      // 4*H
#define D_ 4096    // T*F

typedef unsigned long long ull;

// scratch (__device__ globals; no allocations allowed)
__device__ float g_fc1[B_ * D_];   // relu(x_flat @ fc1_w + b)
__device__ float g_eo[E_ * B_];    // per-expert outputs

// ---------------- helpers -------------------------------------------------
__device__ __forceinline__ ull pack2(float lo, float hi) {
    ull r; asm("mov.b64 %0,{%1,%2};" : "=l"(r) : "f"(lo), "f"(hi)); return r;
}
__device__ __forceinline__ float2 unpack2(ull p) {
    float2 v; asm("mov.b64 {%0,%1},%2;" : "=f"(v.x), "=f"(v.y) : "l"(p)); return v;
}
// packed dual-FMA: d.lo += a.lo*b.lo ; d.hi += a.hi*b.hi   (sm_100+)
__device__ __forceinline__ void ffma2(ull& d, ull a, ull b) {
    asm("fma.rn.f32x2 %0,%1,%2,%0;" : "+l"(d) : "l"(a), "l"(b));
}
__device__ __forceinline__ float sigmoidf_(float x) {
    return 1.0f / (1.0f + __expf(-x));
}
__device__ __forceinline__ uint32_t s2u(const void* p) {
    uint32_t a;
    asm("{ .reg .u64 t; cvta.to.shared.u64 t, %1; cvt.u32.u64 %0, t; }"
        : "=r"(a) : "l"(p));
    return a;
}
__device__ __forceinline__ void cpa16(uint32_t dst, const void* src) {
    asm volatile("cp.async.cg.shared.global [%0],[%1],16;" :: "r"(dst), "l"(src));
}
#define CP_COMMIT() asm volatile("cp.async.commit_group;")
#define CP_WAIT(n)  asm volatile("cp.async.wait_group %0;" :: "n"(n))

// ---------------- K1: fc1 GEMM + fused 2-layer LSTM ------------------------
#define FC1_BLOCKS 256        // 8 M-tiles x 32 N-tiles (128x128x8)
#define LROWS 4               // batch rows per LSTM block
#define LSTM_BLOCKS (E_ * (B_ / LROWS))   // 4096

struct SFC {                        // fc1 tile buffers (24.8 KB)
    float As[2][8][260];            // A duplicated: As[k][2m]=As[k][2m+1]=A[m][k]
    float Ws[2][8][128];
};
struct SPL {                        // fused-lstm buffers
    float bns[F_], bnh[F_];
    float xt[LROWS][F_];            // 128B rows
    float h1[LROWS][24];            // 96B rows; [0..19] live
    float h2[LROWS][24];
    float z1[LROWS][G_];
    float z2[LROWS][G_];
};
union __align__(16) USH { SFC f; SPL p; };

__global__ void __launch_bounds__(320, 2) k1_fc1_lstm(
    const float* __restrict__ x, const float* __restrict__ fc1_w,
    const float* __restrict__ fc1_b,
    const float* __restrict__ bn_gamma, const float* __restrict__ bn_beta,
    const float* __restrict__ bn_mean,  const float* __restrict__ bn_var,
    const float* __restrict__ k1, const float* __restrict__ r1,
    const float* __restrict__ b1,
    const float* __restrict__ k2, const float* __restrict__ r2,
    const float* __restrict__ b2,
    const float* __restrict__ dw, const float* __restrict__ db)
{
    __shared__ USH u;
    const int tid = threadIdx.x;

    if (blockIdx.x < FC1_BLOCKS) {
        // ============== fc1: 128x128x8, FFMA2, cp.async double-buffer ======
        const int m0 = (blockIdx.x >> 5) * 128;
        const int n0 = (blockIdx.x & 31) * 128;
        const bool act = tid < 256;

        const int tx = tid & 15;           // N micro (8 cols)
        const int ty = (tid >> 4) & 15;    // M micro (8 rows)
        const int a_row = tid >> 1;        // 0..127
        const int a_kc  = (tid & 1) * 4;   // 0 or 4
        const int w_row = (tid >> 5) & 7;  // 0..7
        const int w_col = (tid & 31) * 4;  // 0..124

        uint32_t ws0 = s2u(&u.f.Ws[0][w_row][w_col]);
        uint32_t ws1 = s2u(&u.f.Ws[1][w_row][w_col]);
        const float* Asrc = x + (size_t)(m0 + a_row) * D_ + a_kc;
        const float* Wsrc = fc1_w + (size_t)w_row * D_ + n0 + w_col;

        float4 av = make_float4(0, 0, 0, 0);
        if (act) {
            av = *(const float4*)Asrc;
            cpa16(ws0, Wsrc);
            CP_COMMIT();
        }

        ull acc[8][4];
        #pragma unroll
        for (int i = 0; i < 8; i++)
            #pragma unroll
            for (int j = 0; j < 4; j++) acc[i][j] = 0ull;

        const int NS = D_ / 8;   // 512 slabs
        for (int s = 0; s < NS; s++) {
            const int buf = s & 1;
            if (act) {
                *(ull*)&u.f.As[buf][a_kc + 0][2 * a_row] = pack2(av.x, av.x);
                *(ull*)&u.f.As[buf][a_kc + 1][2 * a_row] = pack2(av.y, av.y);
                *(ull*)&u.f.As[buf][a_kc + 2][2 * a_row] = pack2(av.z, av.z);
                *(ull*)&u.f.As[buf][a_kc + 3][2 * a_row] = pack2(av.w, av.w);
                if (s + 1 < NS) {
                    av = *(const float4*)(Asrc + (size_t)(s + 1) * 8);
                    cpa16(buf ? ws0 : ws1, Wsrc + (size_t)(s + 1) * 8 * D_);
                    CP_COMMIT();
                    CP_WAIT(1);
                } else {
                    CP_WAIT(0);
                }
            }
            __syncthreads();
            if (act) {
                #pragma unroll
                for (int k = 0; k < 8; k++) {
                    const ulonglong2* ap =
                        (const ulonglong2*)&u.f.As[buf][k][2 * (ty * 8)];
                    ulonglong2 A0 = ap[0], A1 = ap[1], A2 = ap[2], A3 = ap[3];
                    const ulonglong2* wp =
                        (const ulonglong2*)&u.f.Ws[buf][k][tx * 8];
                    ulonglong2 W0 = wp[0], W1 = wp[1];
                    ull ad[8] = {A0.x, A0.y, A1.x, A1.y, A2.x, A2.y, A3.x, A3.y};
                    #pragma unroll
                    for (int i = 0; i < 8; i++) {
                        ffma2(acc[i][0], ad[i], W0.x);
                        ffma2(acc[i][1], ad[i], W0.y);
                        ffma2(acc[i][2], ad[i], W1.x);
                        ffma2(acc[i][3], ad[i], W1.y);
                    }
                }
            }
            __syncthreads();
        }

        if (act) {
            const int ccol = n0 + tx * 8;
            float bw[8];
            #pragma unroll
            for (int j = 0; j < 8; j++) bw[j] = fc1_b[ccol + j];
            #pragma unroll
            for (int i = 0; i < 8; i++) {
                const int row = m0 + ty * 8 + i;
                float2 c0 = unpack2(acc[i][0]), c1 = unpack2(acc[i][1]);
                float2 c2 = unpack2(acc[i][2]), c3 = unpack2(acc[i][3]);
                float4 o0, o1;
                o0.x = fmaxf(c0.x + bw[0], 0.f); o0.y = fmaxf(c0.y + bw[1], 0.f);
                o0.z = fmaxf(c1.x + bw[2], 0.f); o0.w = fmaxf(c1.y + bw[3], 0.f);
                o1.x = fmaxf(c2.x + bw[4], 0.f); o1.y = fmaxf(c2.y + bw[5], 0.f);
                o1.z = fmaxf(c3.x + bw[6], 0.f); o1.w = fmaxf(c3.y + bw[7], 0.f);
                *(float4*)&g_fc1[(size_t)row * D_ + ccol]     = o0;
                *(float4*)&g_fc1[(size_t)row * D_ + ccol + 4] = o1;
            }
        }
        return;
    }

    // ============== fused 2-layer LSTM, 4 rows/block, skewed pipeline =======
    const int lb = blockIdx.x - FC1_BLOCKS;
    const int e = lb >> 8;                 // 256 row-groups per expert
    const int row0 = (lb & 255) * LROWS;

    const bool isL1 = tid < 160;
    const int v = isL1 ? tid : tid - 160;  // 0..159 within half
    const int rp = (v >= 80) ? 1 : 0;      // row-pair index: rows 2rp, 2rp+1
    const int g = v - rp * 80;             // gate column 0..79

    // cell-update mapping: threads g<40 own cell (row, unit)
    const bool cellth = g < 40;
    const int crow = 2 * rp + (g >= 20 ? 1 : 0);
    const int cunit = (g >= 20) ? g - 20 : g;

    // x stagers: L2-half threads v<128 -> (row v>>5, feature v&31)
    const bool stg = (!isL1) && (v < 128);
    const int srow = v >> 5, sf = v & 31;

    // weight columns, packed into f32x2 pairs over the K index
    ull wa[16], wb[10];
    float bias;
    if (isL1) {
        #pragma unroll
        for (int q = 0; q < 16; q++)
            wa[q] = pack2(k1[(e * F_ + 2 * q) * G_ + g],
                          k1[(e * F_ + 2 * q + 1) * G_ + g]);
        #pragma unroll
        for (int q = 0; q < 10; q++)
            wb[q] = pack2(r1[(e * H_ + 2 * q) * G_ + g],
                          r1[(e * H_ + 2 * q + 1) * G_ + g]);
        bias = b1[e * G_ + g];
    } else {
        #pragma unroll
        for (int q = 0; q < 10; q++)
            wa[q] = pack2(k2[(e * H_ + 2 * q) * G_ + g],
                          k2[(e * H_ + 2 * q + 1) * G_ + g]);
        #pragma unroll
        for (int q = 0; q < 10; q++)
            wb[q] = pack2(r2[(e * H_ + 2 * q) * G_ + g],
                          r2[(e * H_ + 2 * q + 1) * G_ + g]);
        bias = b2[e * G_ + g];
    }

    if (tid < F_) {
        float scv = bn_gamma[tid] * rsqrtf(bn_var[tid] + 1e-3f);
        u.p.bns[tid] = scv;
        u.p.bnh[tid] = bn_beta[tid] - bn_mean[tid] * scv;
    }
    for (int idx = tid; idx < 2 * LROWS * 24; idx += 320)
        ((float*)u.p.h1)[idx] = 0.f;   // h1 + h2 contiguous
    __syncthreads();

    const float* px = x + (size_t)(row0 + srow) * (T_ * F_) + sf;
    float sc = 0.f, sh = 0.f, xv = 0.f;
    if (stg) {
        sc = u.p.bns[sf]; sh = u.p.bnh[sf];
        u.p.xt[srow][sf] = px[0] * sc + sh;   // x(0)
        xv = px[F_];                          // prefetch x(1)
    }
    __syncthreads();

    float c = 0.f;   // cell state for (crow, cunit)

    for (int t = 0; t <= T_; t++) {
        // ---- phase A: gate pre-activations (2 rows per thread) ----
        if (isL1) {
            if (t < T_) {
                #pragma unroll
                for (int i = 0; i < 2; i++) {
                    const int row = 2 * rp + i;
                    ull a0 = pack2(bias, 0.f), a1 = 0, a2 = 0, a3 = 0;
                    const ulonglong2* xr = (const ulonglong2*)u.p.xt[row];
                    #pragma unroll
                    for (int q = 0; q < 8; q++) {
                        ulonglong2 X = xr[q];
                        if ((2 * q) & 2) { ffma2(a2, X.x, wa[2 * q]); ffma2(a3, X.y, wa[2 * q + 1]); }
                        else             { ffma2(a0, X.x, wa[2 * q]); ffma2(a1, X.y, wa[2 * q + 1]); }
                    }
                    const ull* hp = (const ull*)u.p.h1[row];
                    #pragma unroll
                    for (int q = 0; q < 10; q++) {
                        ull hv = hp[q];
                        if (q & 2) { if (q & 1) ffma2(a3, hv, wb[q]); else ffma2(a2, hv, wb[q]); }
                        else       { if (q & 1) ffma2(a1, hv, wb[q]); else ffma2(a0, hv, wb[q]); }
                    }
                    float2 s0 = unpack2(a0), s1 = unpack2(a1);
                    float2 s2 = unpack2(a2), s3 = unpack2(a3);
                    u.p.z1[row][g] = ((s0.x + s0.y) + (s1.x + s1.y)) +
                                     ((s2.x + s2.y) + (s3.x + s3.y));
                }
            }
        } else {
            if (t >= 1) {
                #pragma unroll
                for (int i = 0; i < 2; i++) {
                    const int row = 2 * rp + i;
                    ull a0 = pack2(bias, 0.f), a1 = 0, a2 = 0, a3 = 0;
                    const ull* h1p = (const ull*)u.p.h1[row];
                    const ull* h2p = (const ull*)u.p.h2[row];
                    #pragma unroll
                    for (int q = 0; q < 10; q++) {
                        ull hv1 = h1p[q], hv2 = h2p[q];
                        if (q & 1) { ffma2(a1, hv1, wa[q]); ffma2(a3, hv2, wb[q]); }
                        else       { ffma2(a0, hv1, wa[q]); ffma2(a2, hv2, wb[q]); }
                    }
                    float2 s0 = unpack2(a0), s1 = unpack2(a1);
                    float2 s2 = unpack2(a2), s3 = unpack2(a3);
                    u.p.z2[row][g] = ((s0.x + s0.y) + (s1.x + s1.y)) +
                                     ((s2.x + s2.y) + (s3.x + s3.y));
                }
            }
        }
        __syncthreads();

        // ---- phase B: cell updates + x staging ----
        if (isL1) {
            if (cellth && t < T_) {
                float zi = u.p.z1[crow][cunit];
                float zf = u.p.z1[crow][H_ + cunit];
                float zg = u.p.z1[crow][2 * H_ + cunit];
                float zo = u.p.z1[crow][3 * H_ + cunit];
                c = sigmoidf_(zf) * c + sigmoidf_(zi) * fmaxf(zg, 0.f);
                u.p.h1[crow][cunit] = sigmoidf_(zo) * fmaxf(c, 0.f);
            }
        } else {
            if (cellth && t >= 1) {
                float zi = u.p.z2[crow][cunit];
                float zf = u.p.z2[crow][H_ + cunit];
                float zg = u.p.z2[crow][2 * H_ + cunit];
                float zo = u.p.z2[crow][3 * H_ + cunit];
                c = sigmoidf_(zf) * c + sigmoidf_(zi) * fmaxf(zg, 0.f);
                u.p.h2[crow][cunit] = sigmoidf_(zo) * fmaxf(c, 0.f);
            }
            if (stg && t + 1 < T_) {
                u.p.xt[srow][sf] = xv * sc + sh;                // x(t+1)
                int tn = (t + 2 < T_) ? t + 2 : T_ - 1;
                xv = px[(size_t)tn * F_];
            }
        }
        __syncthreads();
    }

    // dense head: eo[e,b] = h2(T-1) @ dw[e] + db[e]
    if (!isL1 && v < LROWS) {
        float acc = db[e];
        #pragma unroll
        for (int j = 0; j < H_; j++) acc += u.p.h2[v][j] * dw[e * H_ + j];
        g_eo[e * B_ + row0 + v] = acc;
    }
}

// ---------------- K2: gate (fc1 row @ gate_w, softmax) + combine ----------
__global__ void __launch_bounds__(320) k2_gate_combine(
    const float* __restrict__ GW, const float* __restrict__ GB,
    float* __restrict__ out)
{
    __shared__ float red[10][E_];
    __shared__ float sv[E_];
    __shared__ float ev[E_];
    __shared__ float part[E_];

    const int b = blockIdx.x;
    const int tid = threadIdx.x;
    float acc[E_];
    #pragma unroll
    for (int e = 0; e < E_; e++) acc[e] = 0.f;

    const float* grow = g_fc1 + (size_t)b * D_;
    for (int k = tid; k < D_; k += 320) {
        float gv = grow[k];
        const float4* wp = (const float4*)(GW + (size_t)k * E_);
        float4 w0 = wp[0], w1 = wp[1], w2 = wp[2], w3 = wp[3];
        acc[0]  += gv * w0.x;  acc[1]  += gv * w0.y;
        acc[2]  += gv * w0.z;  acc[3]  += gv * w0.w;
        acc[4]  += gv * w1.x;  acc[5]  += gv * w1.y;
        acc[6]  += gv * w1.z;  acc[7]  += gv * w1.w;
        acc[8]  += gv * w2.x;  acc[9]  += gv * w2.y;
        acc[10] += gv * w2.z;  acc[11] += gv * w2.w;
        acc[12] += gv * w3.x;  acc[13] += gv * w3.y;
        acc[14] += gv * w3.z;  acc[15] += gv * w3.w;
    }
    #pragma unroll
    for (int e = 0; e < E_; e++) {
        #pragma unroll
        for (int off = 16; off > 0; off >>= 1)
            acc[e] += __shfl_down_sync(0xffffffffu, acc[e], off);
    }
    const int warp = tid >> 5, lane = tid & 31;
    if (lane == 0) {
        #pragma unroll
        for (int e = 0; e < E_; e++) red[warp][e] = acc[e];
    }
    __syncthreads();
    if (tid < E_) {
        float s = GB[tid];
        #pragma unroll
        for (int w = 0; w < 10; w++) s += red[w][tid];
        sv[tid] = s;
    }
    __syncthreads();
    if (tid < E_) {
        float m = sv[0];
        #pragma unroll
        for (int e = 1; e < E_; e++) m = fmaxf(m, sv[e]);
        ev[tid] = expf(sv[tid] - m);
    }
    __syncthreads();
    if (tid < E_) {
        float s = 0.f;
        #pragma unroll
        for (int e = 0; e < E_; e++) s += ev[e];
        part[tid] = (ev[tid] / s) * g_eo[tid * B_ + b];
    }
    __syncthreads();
    if (tid == 0) {
        float s = 0.f;
        #pragma unroll
        for (int e = 0; e < E_; e++) s += part[e];
        out[b] = s;
    }
}

// ---------------------------------------------------------------------------
extern "C" void kernel_launch(void* const* d_in, const int* in_sizes, int n_in,
                              void* d_out, int out_size)
{
    const float* x        = (const float*)d_in[0];
    const float* bn_gamma = (const float*)d_in[1];
    const float* bn_beta  = (const float*)d_in[2];
    const float* bn_mean  = (const float*)d_in[3];
    const float* bn_var   = (const float*)d_in[4];
    const float* k1       = (const float*)d_in[5];
    const float* r1       = (const float*)d_in[6];
    const float* b1       = (const float*)d_in[7];
    const float* k2       = (const float*)d_in[8];
    const float* r2       = (const float*)d_in[9];
    const float* b2       = (const float*)d_in[10];
    const float* dw       = (const float*)d_in[11];
    const float* db       = (const float*)d_in[12];
    const float* fc1_w    = (const float*)d_in[13];
    const float* fc1_b    = (const float*)d_in[14];
    const float* gate_w   = (const float*)d_in[15];
    const float* gate_b   = (const float*)d_in[16];
    float* out = (float*)d_out;

    k1_fc1_lstm<<<FC1_BLOCKS + LSTM_BLOCKS, 320>>>(
        x, fc1_w, fc1_b, bn_gamma, bn_beta, bn_mean, bn_var,
        k1, r1, b1, k2, r2, b2, dw, db);

    k2_gate_combine<<<B_, 320>>>(gate_w, gate_b, out);
}

// round 6
// speedup vs baseline: 2.6923x; 1.3958x over previous
#include <cuda_runtime.h>
#include <math.h>
#include <stdint.h>

#define B_ 1024
#define T_ 128
#define F_ 32
#define E_ 16
#define H_ 20
#define G_ 80      // 4*H
#define D_ 4096    // T*F

typedef unsigned long long ull;

// scratch (__device__ globals; no allocations allowed)
__device__ float g_fc1[B_ * D_];   // relu(x_flat @ fc1_w + b)
__device__ float g_eo[E_ * B_];    // per-expert outputs

// ---------------- helpers -------------------------------------------------
__device__ __forceinline__ ull pack2(float lo, float hi) {
    ull r; asm("mov.b64 %0,{%1,%2};" : "=l"(r) : "f"(lo), "f"(hi)); return r;
}
__device__ __forceinline__ float2 unpack2(ull p) {
    float2 v; asm("mov.b64 {%0,%1},%2;" : "=f"(v.x), "=f"(v.y) : "l"(p)); return v;
}
__device__ __forceinline__ void ffma2(ull& d, ull a, ull b) {
    asm("fma.rn.f32x2 %0,%1,%2,%0;" : "+l"(d) : "l"(a), "l"(b));
}
__device__ __forceinline__ float sigmoidf_(float x) {
    return 1.0f / (1.0f + __expf(-x));
}
__device__ __forceinline__ uint32_t f2tf32(float x) {
    uint32_t r; asm("cvt.rna.tf32.f32 %0, %1;" : "=r"(r) : "f"(x)); return r;
}
// D += A(tf32) * B(tf32), m16n8k8
__device__ __forceinline__ void mma_tf32(float* c, const uint32_t* a, const uint32_t* b) {
    asm("mma.sync.aligned.m16n8k8.row.col.f32.tf32.tf32.f32 "
        "{%0,%1,%2,%3},{%4,%5,%6,%7},{%8,%9},{%0,%1,%2,%3};"
        : "+f"(c[0]), "+f"(c[1]), "+f"(c[2]), "+f"(c[3])
        : "r"(a[0]), "r"(a[1]), "r"(a[2]), "r"(a[3]), "r"(b[0]), "r"(b[1]));
}

// ---------------- K1: fc1 tf32-split tensor GEMM + fused 2-layer LSTM ------
#define FC1_BLOCKS 512        // 8 M-tiles x 64 N-tiles (128x64), Kslab=16
#define LROWS 8               // batch rows per LSTM block
#define LSTM_BLOCKS (E_ * (B_ / LROWS))   // 2048

struct SFC {                        // fc1 tile buffers (~29.7 KB)
    uint32_t Ah[128][20];           // tf32-hi A slab, padded stride 20
    uint32_t Al[128][20];           // tf32-lo
    uint32_t Bh[16][72];            // tf32-hi B slab, padded stride 72
    uint32_t Bl[16][72];
};
struct SPL {                        // fused-lstm buffers (~8 KB)
    float bns[F_], bnh[F_];
    float xt[LROWS][F_];
    float h1[LROWS][24];            // [0..19] live
    float h2[LROWS][24];
    float z1[LROWS][G_];
    float z2[LROWS][G_];
};
union __align__(16) USH { SFC f; SPL p; };

__global__ void __launch_bounds__(320, 2) k1_fc1_lstm(
    const float* __restrict__ x, const float* __restrict__ fc1_w,
    const float* __restrict__ fc1_b,
    const float* __restrict__ bn_gamma, const float* __restrict__ bn_beta,
    const float* __restrict__ bn_mean,  const float* __restrict__ bn_var,
    const float* __restrict__ k1, const float* __restrict__ r1,
    const float* __restrict__ b1,
    const float* __restrict__ k2, const float* __restrict__ r2,
    const float* __restrict__ b2,
    const float* __restrict__ dw, const float* __restrict__ db)
{
    __shared__ USH u;
    const int tid = threadIdx.x;

    if (blockIdx.x < FC1_BLOCKS) {
        // ======== fc1: 128x64 block, mma.sync tf32 hi/lo split (3 passes) ===
        const int m0 = (blockIdx.x >> 6) * 128;
        const int n0 = (blockIdx.x & 63) * 64;
        const bool act = tid < 256;
        const int lane = tid & 31;
        const int wid = tid >> 5;            // 0..9; warps 8,9 idle
        const int g  = lane >> 2;            // 0..7
        const int tg = lane & 3;             // 0..3
        const int warp_m = wid & 3;          // 4 warps in M
        const int warp_n = (wid >> 2) & 1;   // 2 warps in N

        // global staging indices
        const int a_row = tid >> 1;          // 0..127
        const int a_kc  = (tid & 1) * 8;     // 0 or 8
        const int b_k   = tid >> 4;          // 0..15
        const int b_nc  = (tid & 15) * 4;    // 0..60

        const float* Ap = x + (size_t)(m0 + a_row) * D_ + a_kc;
        const float* Bp = fc1_w + (size_t)b_k * D_ + n0 + b_nc;

        float4 av0, av1, bv;
        if (act) {
            av0 = *(const float4*)Ap;
            av1 = *(const float4*)(Ap + 4);
            bv  = *(const float4*)Bp;
        }

        float c[2][4][4];
        #pragma unroll
        for (int mt = 0; mt < 2; mt++)
            #pragma unroll
            for (int nt = 0; nt < 4; nt++)
                #pragma unroll
                for (int j = 0; j < 4; j++) c[mt][nt][j] = 0.f;

        const int NS = D_ / 16;   // 256 slabs
        for (int s = 0; s < NS; s++) {
            if (act) {
                // convert + store A slab (hi/lo) -- register arrays, no UB
                float af[8] = {av0.x, av0.y, av0.z, av0.w, av1.x, av1.y, av1.z, av1.w};
                uint32_t hh[8], ll[8];
                #pragma unroll
                for (int j = 0; j < 8; j++) {
                    uint32_t hi = f2tf32(af[j]);
                    float lo = af[j] - __uint_as_float(hi);
                    hh[j] = hi;
                    ll[j] = f2tf32(lo);
                }
                *(uint4*)&u.f.Ah[a_row][a_kc]     = make_uint4(hh[0], hh[1], hh[2], hh[3]);
                *(uint4*)&u.f.Ah[a_row][a_kc + 4] = make_uint4(hh[4], hh[5], hh[6], hh[7]);
                *(uint4*)&u.f.Al[a_row][a_kc]     = make_uint4(ll[0], ll[1], ll[2], ll[3]);
                *(uint4*)&u.f.Al[a_row][a_kc + 4] = make_uint4(ll[4], ll[5], ll[6], ll[7]);
                // convert + store B slab
                float bf[4] = {bv.x, bv.y, bv.z, bv.w};
                uint32_t bhh[4], bll[4];
                #pragma unroll
                for (int j = 0; j < 4; j++) {
                    uint32_t hi = f2tf32(bf[j]);
                    float lo = bf[j] - __uint_as_float(hi);
                    bhh[j] = hi;
                    bll[j] = f2tf32(lo);
                }
                *(uint4*)&u.f.Bh[b_k][b_nc] = make_uint4(bhh[0], bhh[1], bhh[2], bhh[3]);
                *(uint4*)&u.f.Bl[b_k][b_nc] = make_uint4(bll[0], bll[1], bll[2], bll[3]);
            }
            __syncthreads();
            if (act && s + 1 < NS) {
                av0 = *(const float4*)(Ap + (size_t)(s + 1) * 16);
                av1 = *(const float4*)(Ap + (size_t)(s + 1) * 16 + 4);
                bv  = *(const float4*)(Bp + (size_t)(s + 1) * 16 * D_);
            }
            if (act && wid < 8) {
                #pragma unroll
                for (int kk = 0; kk < 16; kk += 8) {
                    uint32_t ah[2][4], al[2][4], bh[4][2], bl[4][2];
                    #pragma unroll
                    for (int mt = 0; mt < 2; mt++) {
                        const int ar = warp_m * 32 + mt * 16 + g;
                        ah[mt][0] = u.f.Ah[ar][kk + tg];
                        ah[mt][1] = u.f.Ah[ar + 8][kk + tg];
                        ah[mt][2] = u.f.Ah[ar][kk + tg + 4];
                        ah[mt][3] = u.f.Ah[ar + 8][kk + tg + 4];
                        al[mt][0] = u.f.Al[ar][kk + tg];
                        al[mt][1] = u.f.Al[ar + 8][kk + tg];
                        al[mt][2] = u.f.Al[ar][kk + tg + 4];
                        al[mt][3] = u.f.Al[ar + 8][kk + tg + 4];
                    }
                    #pragma unroll
                    for (int nt = 0; nt < 4; nt++) {
                        const int bc = warp_n * 32 + nt * 8 + g;
                        bh[nt][0] = u.f.Bh[kk + tg][bc];
                        bh[nt][1] = u.f.Bh[kk + tg + 4][bc];
                        bl[nt][0] = u.f.Bl[kk + tg][bc];
                        bl[nt][1] = u.f.Bl[kk + tg + 4][bc];
                    }
                    #pragma unroll
                    for (int mt = 0; mt < 2; mt++)
                        #pragma unroll
                        for (int nt = 0; nt < 4; nt++) {
                            mma_tf32(c[mt][nt], ah[mt], bh[nt]);   // hi*hi
                            mma_tf32(c[mt][nt], ah[mt], bl[nt]);   // hi*lo
                            mma_tf32(c[mt][nt], al[mt], bh[nt]);   // lo*hi
                        }
                }
            }
            __syncthreads();
        }

        if (act && wid < 8) {
            #pragma unroll
            for (int mt = 0; mt < 2; mt++) {
                #pragma unroll
                for (int nt = 0; nt < 4; nt++) {
                    const int row = m0 + warp_m * 32 + mt * 16 + g;
                    const int col = n0 + warp_n * 32 + nt * 8 + 2 * tg;
                    float2 bb = *(const float2*)&fc1_b[col];
                    float2 o0, o1;
                    o0.x = fmaxf(c[mt][nt][0] + bb.x, 0.f);
                    o0.y = fmaxf(c[mt][nt][1] + bb.y, 0.f);
                    o1.x = fmaxf(c[mt][nt][2] + bb.x, 0.f);
                    o1.y = fmaxf(c[mt][nt][3] + bb.y, 0.f);
                    *(float2*)&g_fc1[(size_t)row * D_ + col]       = o0;
                    *(float2*)&g_fc1[(size_t)(row + 8) * D_ + col] = o1;
                }
            }
        }
        return;
    }

    // ============== fused 2-layer LSTM, 8 rows/block, skewed pipeline =======
    const int lb = blockIdx.x - FC1_BLOCKS;
    const int e = lb >> 7;                 // 128 row-groups per expert
    const int row0 = (lb & 127) * LROWS;

    const bool isL1 = tid < 160;
    const int v = isL1 ? tid : tid - 160;  // 0..159 within half
    const int rp = (v >= 80) ? 1 : 0;      // row group: rows 4rp..4rp+3
    const int g = v - rp * 80;             // gate column 0..79

    // cell-update mapping: 160 cells per half = 8 rows x 20 units, 1/thread
    const int crow = v / 20;
    const int cunit = v - crow * 20;

    // x stagers: tid<256 -> (row tid>>5, feature tid&31)
    const bool stg = tid < 256;
    const int srow = tid >> 5, sf = tid & 31;

    // weight columns, packed into f32x2 pairs over the K index
    ull wa[16], wb[10];
    float bias;
    if (isL1) {
        #pragma unroll
        for (int q = 0; q < 16; q++)
            wa[q] = pack2(k1[(e * F_ + 2 * q) * G_ + g],
                          k1[(e * F_ + 2 * q + 1) * G_ + g]);
        #pragma unroll
        for (int q = 0; q < 10; q++)
            wb[q] = pack2(r1[(e * H_ + 2 * q) * G_ + g],
                          r1[(e * H_ + 2 * q + 1) * G_ + g]);
        bias = b1[e * G_ + g];
    } else {
        #pragma unroll
        for (int q = 0; q < 10; q++)
            wa[q] = pack2(k2[(e * H_ + 2 * q) * G_ + g],
                          k2[(e * H_ + 2 * q + 1) * G_ + g]);
        #pragma unroll
        for (int q = 0; q < 10; q++)
            wb[q] = pack2(r2[(e * H_ + 2 * q) * G_ + g],
                          r2[(e * H_ + 2 * q + 1) * G_ + g]);
        bias = b2[e * G_ + g];
    }

    if (tid < F_) {
        float scv = bn_gamma[tid] * rsqrtf(bn_var[tid] + 1e-3f);
        u.p.bns[tid] = scv;
        u.p.bnh[tid] = bn_beta[tid] - bn_mean[tid] * scv;
    }
    for (int idx = tid; idx < 2 * LROWS * 24; idx += 320)
        ((float*)u.p.h1)[idx] = 0.f;   // h1 + h2 contiguous
    __syncthreads();

    const float* px = x + (size_t)(row0 + srow) * (T_ * F_) + sf;
    float sc = 0.f, sh = 0.f, xv = 0.f;
    if (stg) {
        sc = u.p.bns[sf]; sh = u.p.bnh[sf];
        u.p.xt[srow][sf] = px[0] * sc + sh;   // x(0)
        xv = px[F_];                          // prefetch x(1)
    }
    __syncthreads();

    float c = 0.f;   // cell state for (crow, cunit)

    for (int t = 0; t <= T_; t++) {
        // ---- phase A: gate pre-activations (4 rows per thread) ----
        if (isL1) {
            if (t < T_) {
                #pragma unroll
                for (int i = 0; i < 4; i++) {
                    const int row = 4 * rp + i;
                    ull a0 = pack2(bias, 0.f), a1 = 0, a2 = 0, a3 = 0;
                    const ulonglong2* xr = (const ulonglong2*)u.p.xt[row];
                    #pragma unroll
                    for (int q = 0; q < 8; q++) {
                        ulonglong2 X = xr[q];
                        if ((2 * q) & 2) { ffma2(a2, X.x, wa[2 * q]); ffma2(a3, X.y, wa[2 * q + 1]); }
                        else             { ffma2(a0, X.x, wa[2 * q]); ffma2(a1, X.y, wa[2 * q + 1]); }
                    }
                    const ull* hp = (const ull*)u.p.h1[row];
                    #pragma unroll
                    for (int q = 0; q < 10; q++) {
                        ull hv = hp[q];
                        if (q & 2) { if (q & 1) ffma2(a3, hv, wb[q]); else ffma2(a2, hv, wb[q]); }
                        else       { if (q & 1) ffma2(a1, hv, wb[q]); else ffma2(a0, hv, wb[q]); }
                    }
                    float2 s0 = unpack2(a0), s1 = unpack2(a1);
                    float2 s2 = unpack2(a2), s3 = unpack2(a3);
                    u.p.z1[row][g] = ((s0.x + s0.y) + (s1.x + s1.y)) +
                                     ((s2.x + s2.y) + (s3.x + s3.y));
                }
            }
        } else {
            if (t >= 1) {
                #pragma unroll
                for (int i = 0; i < 4; i++) {
                    const int row = 4 * rp + i;
                    ull a0 = pack2(bias, 0.f), a1 = 0, a2 = 0, a3 = 0;
                    const ull* h1p = (const ull*)u.p.h1[row];
                    const ull* h2p = (const ull*)u.p.h2[row];
                    #pragma unroll
                    for (int q = 0; q < 10; q++) {
                        ull hv1 = h1p[q], hv2 = h2p[q];
                        if (q & 1) { ffma2(a1, hv1, wa[q]); ffma2(a3, hv2, wb[q]); }
                        else       { ffma2(a0, hv1, wa[q]); ffma2(a2, hv2, wb[q]); }
                    }
                    float2 s0 = unpack2(a0), s1 = unpack2(a1);
                    float2 s2 = unpack2(a2), s3 = unpack2(a3);
                    u.p.z2[row][g] = ((s0.x + s0.y) + (s1.x + s1.y)) +
                                     ((s2.x + s2.y) + (s3.x + s3.y));
                }
            }
        }
        __syncthreads();

        // ---- phase B: cell updates (1 cell/thread) + x staging ----
        if (isL1) {
            if (t < T_) {
                float zi = u.p.z1[crow][cunit];
                float zf = u.p.z1[crow][H_ + cunit];
                float zg = u.p.z1[crow][2 * H_ + cunit];
                float zo = u.p.z1[crow][3 * H_ + cunit];
                c = sigmoidf_(zf) * c + sigmoidf_(zi) * fmaxf(zg, 0.f);
                u.p.h1[crow][cunit] = sigmoidf_(zo) * fmaxf(c, 0.f);
            }
        } else {
            if (t >= 1) {
                float zi = u.p.z2[crow][cunit];
                float zf = u.p.z2[crow][H_ + cunit];
                float zg = u.p.z2[crow][2 * H_ + cunit];
                float zo = u.p.z2[crow][3 * H_ + cunit];
                c = sigmoidf_(zf) * c + sigmoidf_(zi) * fmaxf(zg, 0.f);
                u.p.h2[crow][cunit] = sigmoidf_(zo) * fmaxf(c, 0.f);
            }
        }
        if (stg && t + 1 < T_) {
            u.p.xt[srow][sf] = xv * sc + sh;                // x(t+1)
            int tn = (t + 2 < T_) ? t + 2 : T_ - 1;
            xv = px[(size_t)tn * F_];
        }
        __syncthreads();
    }

    // dense head: eo[e,b] = h2(T-1) @ dw[e] + db[e]
    if (!isL1 && v < LROWS) {
        float acc = db[e];
        #pragma unroll
        for (int j = 0; j < H_; j++) acc += u.p.h2[v][j] * dw[e * H_ + j];
        g_eo[e * B_ + row0 + v] = acc;
    }
}

// ---------------- K2: gate (fc1 row @ gate_w, softmax) + combine ----------
__global__ void __launch_bounds__(320) k2_gate_combine(
    const float* __restrict__ GW, const float* __restrict__ GB,
    float* __restrict__ out)
{
    __shared__ float red[10][E_];
    __shared__ float sv[E_];
    __shared__ float ev[E_];
    __shared__ float part[E_];

    const int b = blockIdx.x;
    const int tid = threadIdx.x;
    float acc[E_];
    #pragma unroll
    for (int e = 0; e < E_; e++) acc[e] = 0.f;

    const float* grow = g_fc1 + (size_t)b * D_;
    for (int k = tid; k < D_; k += 320) {
        float gv = grow[k];
        const float4* wp = (const float4*)(GW + (size_t)k * E_);
        float4 w0 = wp[0], w1 = wp[1], w2 = wp[2], w3 = wp[3];
        acc[0]  += gv * w0.x;  acc[1]  += gv * w0.y;
        acc[2]  += gv * w0.z;  acc[3]  += gv * w0.w;
        acc[4]  += gv * w1.x;  acc[5]  += gv * w1.y;
        acc[6]  += gv * w1.z;  acc[7]  += gv * w1.w;
        acc[8]  += gv * w2.x;  acc[9]  += gv * w2.y;
        acc[10] += gv * w2.z;  acc[11] += gv * w2.w;
        acc[12] += gv * w3.x;  acc[13] += gv * w3.y;
        acc[14] += gv * w3.z;  acc[15] += gv * w3.w;
    }
    #pragma unroll
    for (int e = 0; e < E_; e++) {
        #pragma unroll
        for (int off = 16; off > 0; off >>= 1)
            acc[e] += __shfl_down_sync(0xffffffffu, acc[e], off);
    }
    const int warp = tid >> 5, lane = tid & 31;
    if (lane == 0) {
        #pragma unroll
        for (int e = 0; e < E_; e++) red[warp][e] = acc[e];
    }
    __syncthreads();
    if (tid < E_) {
        float s = GB[tid];
        #pragma unroll
        for (int w = 0; w < 10; w++) s += red[w][tid];
        sv[tid] = s;
    }
    __syncthreads();
    if (tid < E_) {
        float m = sv[0];
        #pragma unroll
        for (int e = 1; e < E_; e++) m = fmaxf(m, sv[e]);
        ev[tid] = expf(sv[tid] - m);
    }
    __syncthreads();
    if (tid < E_) {
        float s = 0.f;
        #pragma unroll
        for (int e = 0; e < E_; e++) s += ev[e];
        part[tid] = (ev[tid] / s) * g_eo[tid * B_ + b];
    }
    __syncthreads();
    if (tid == 0) {
        float s = 0.f;
        #pragma unroll
        for (int e = 0; e < E_; e++) s += part[e];
        out[b] = s;
    }
}

// ---------------------------------------------------------------------------
extern "C" void kernel_launch(void* const* d_in, const int* in_sizes, int n_in,
                              void* d_out, int out_size)
{
    const float* x        = (const float*)d_in[0];
    const float* bn_gamma = (const float*)d_in[1];
    const float* bn_beta  = (const float*)d_in[2];
    const float* bn_mean  = (const float*)d_in[3];
    const float* bn_var   = (const float*)d_in[4];
    const float* k1       = (const float*)d_in[5];
    const float* r1       = (const float*)d_in[6];
    const float* b1       = (const float*)d_in[7];
    const float* k2       = (const float*)d_in[8];
    const float* r2       = (const float*)d_in[9];
    const float* b2       = (const float*)d_in[10];
    const float* dw       = (const float*)d_in[11];
    const float* db       = (const float*)d_in[12];
    const float* fc1_w    = (const float*)d_in[13];
    const float* fc1_b    = (const float*)d_in[14];
    const float* gate_w   = (const float*)d_in[15];
    const float* gate_b   = (const float*)d_in[16];
    float* out = (float*)d_out;

    k1_fc1_lstm<<<FC1_BLOCKS + LSTM_BLOCKS, 320>>>(
        x, fc1_w, fc1_b, bn_gamma, bn_beta, bn_mean, bn_var,
        k1, r1, b1, k2, r2, b2, dw, db);

    k2_gate_combine<<<B_, 320>>>(gate_w, gate_b, out);
}